// round 3
// baseline (speedup 1.0000x reference)
#include <cuda_runtime.h>

#define HH 1024
#define WW 2048
#define HWTOT (HH * WW)
#define NBLK 2048

#define FLUXC    0.87890625f              // 300*H_STEP
#define F_COEF   0.002574920654296875f    // FLUX*H_STEP
#define WC0V_F ((float)(651.83 * 202.412 * 0.001 / 2.0))

// Cubic Taylor of K(tc) = FLUX0/(cp_a+cp_v*x_a)*(x_v-x_a)*C1*C2*C4*CT  about tc=0 (t=273.15K)
#define K_C0 (-5.517e-4f)
#define K_C1 ( 4.242e-5f)
#define K_C2 ( 1.399e-6f)
#define K_C3 ( 2.569e-8f)

// direction masks: extras per eq-code
#define CXP_MASK ((1u<<4)|(1u<<9)|(1u<<10))
#define CXN_MASK ((1u<<6)|(1u<<8)|(1u<<11))
#define CYP_MASK ((1u<<7)|(1u<<8)|(1u<<9))
#define CYN_MASK ((1u<<5)|(1u<<10)|(1u<<11))

__device__ float4 g_part[NBLK];          // per-block {S0, S1, S2, Swc}
__device__ unsigned int g_count = 0;     // arrival counter (reset by last block)

__device__ __forceinline__ int b_val(int raw, int r, int c) {
    if (r == 0 || r == HH - 1) return 3;
    if (c == WW - 1) return 3;
    if (c == 1) return 0;
    if ((r == 1 || r == HH - 2) && c >= 2) return 0;
    return raw;
}

__global__ __launch_bounds__(256) void energy_evp_main(
    const int*   __restrict__ layout,
    const float* __restrict__ heat_ini,
    const float* __restrict__ wc,
    const float* __restrict__ heat,
    const float* __restrict__ flow,
    float*       __restrict__ out)
{
    const int g = blockIdx.x * blockDim.x + threadIdx.x;
    const int base = g * 4;
    const int r  = base >> 11;          // / WW
    const int c0 = base & (WW - 1);

    const int* __restrict__ braw = layout + HWTOT;

    const int4   b4  = *(const int4*)(braw + base);
    const int4   g4  = *(const int4*)(layout + base);
    const float4 h4  = *(const float4*)(heat + base);
    const float4 hi4 = *(const float4*)(heat_ini + base);
    const float4 w4  = *(const float4*)(wc + base);
    const float4 u4  = *(const float4*)(flow + base);
    const float4 v4  = *(const float4*)(flow + HWTOT + base);

    const int   brs[4] = {b4.x, b4.y, b4.z, b4.w};
    const int   ggs[4] = {g4.x, g4.y, g4.z, g4.w};
    const float hs[4]  = {h4.x, h4.y, h4.z, h4.w};
    const float his[4] = {hi4.x, hi4.y, hi4.z, hi4.w};
    const float ws[4]  = {w4.x, w4.y, w4.z, w4.w};
    const float us[4]  = {u4.x, u4.y, u4.z, u4.w};
    const float vs[4]  = {v4.x, v4.y, v4.z, v4.w};

    int   bs[4];
    float hb[4];
#pragma unroll
    for (int j = 0; j < 4; j++) {
        bs[j] = b_val(brs[j], r, c0 + j);
        hb[j] = (bs[j] == 1) ? 0.f : hs[j];
    }

    // heat_bc over columns c0-1 .. c0+4
    float hbx[6];
#pragma unroll
    for (int j = 0; j < 4; j++) hbx[j + 1] = hb[j];
    if (c0 > 0) {
        int bl = b_val(braw[base - 1], r, c0 - 1);
        hbx[0] = (bl == 1) ? 0.f : heat[base - 1];
    } else hbx[0] = 0.f;
    if (c0 + 4 < WW) {
        int br_ = b_val(braw[base + 4], r, c0 + 4);
        hbx[5] = (br_ == 1) ? 0.f : heat[base + 4];
    } else hbx[5] = 0.f;

    // vertical neighbors (dy = 0 on first/last row via reflect pad)
    const bool has_y = (r > 0) && (r < HH - 1);
    float hbu[4] = {0.f, 0.f, 0.f, 0.f};
    float hbd[4] = {0.f, 0.f, 0.f, 0.f};
    if (has_y) {
        const int4   bu4 = *(const int4*)(braw + base - WW);
        const int4   bd4 = *(const int4*)(braw + base + WW);
        const float4 hu4 = *(const float4*)(heat + base - WW);
        const float4 hd4 = *(const float4*)(heat + base + WW);
        const int bus[4] = {bu4.x, bu4.y, bu4.z, bu4.w};
        const int bds[4] = {bd4.x, bd4.y, bd4.z, bd4.w};
        const float hus[4] = {hu4.x, hu4.y, hu4.z, hu4.w};
        const float hds[4] = {hd4.x, hd4.y, hd4.z, hd4.w};
#pragma unroll
        for (int j = 0; j < 4; j++) {
            hbu[j] = (b_val(bus[j], r - 1, c0 + j) == 1) ? 0.f : hus[j];
            hbd[j] = (b_val(bds[j], r + 1, c0 + j) == 1) ? 0.f : hds[j];
        }
    }

    float d0 = 0.f, d1 = 0.f, d2 = 0.f, d3 = 0.f;
    const bool edge_row = (r == 0) || (r == HH - 1);

#pragma unroll
    for (int j = 0; j < 4; j++) {
        const int c = c0 + j;
        const int b = bs[j];

        const float dx = (c == 0 || c == WW - 1) ? 0.f : 0.5f * (hbx[j + 2] - hbx[j]);
        const float dy = has_y ? 0.5f * (hbd[j] - hbu[j]) : 0.f;

        const float geom = edge_row ? 1.f : (float)ggs[j];
        const float f    = fabsf(geom - 1.f) * F_COEF;

        const float ad = his[j] - 0.001f * (us[j] * dx + vs[j] * dy);

        const float wcm  = (b > 3) ? 1.f : 0.f;
        const float wcbc = ws[j] * wcm;
        d3 += wcbc;

        // K(tc): cubic Taylor, tc = heat_bc (Celsius). m_dot = C3 * K.
        const float tc = hb[j];
        const float K  = fmaf(fmaf(fmaf(K_C3, tc, K_C2), tc, K_C1), tc, K_C0);

        // direction coefficients via bitmasks (no local-memory tables)
        const float cx = (float)(int)((CXP_MASK >> b) & 1u) - (float)(int)((CXN_MASK >> b) & 1u);
        const float cy = (float)(int)((CYP_MASK >> b) & 1u) - (float)(int)((CYN_MASK >> b) & 1u);
        const float al = (b >= 4) ? 1.f : 0.f;

        float A, Bc;
        if (b == 1) {
            A = -f; Bc = 0.f;
        } else {
            A  = ad + FLUXC * (cx * dx + cy * dy) + al * WC0V_F - f;
            Bc = -0.001f * al * K;
        }
        const float Aw = WC0V_F * wcm - wcbc;
        const float Bw = -K;

        d0 += A * A + Aw * Aw;
        d1 += 2.f * (A * Bc + Aw * Bw);
        d2 += Bc * Bc + Bw * Bw;

        out[1 + base + j]         = hb[j];
        out[1 + HWTOT + base + j] = (float)((b == 1) ? 0 : b);
    }

    // warp tree reduce (float)
#pragma unroll
    for (int o = 16; o > 0; o >>= 1) {
        d0 += __shfl_down_sync(0xffffffffu, d0, o);
        d1 += __shfl_down_sync(0xffffffffu, d1, o);
        d2 += __shfl_down_sync(0xffffffffu, d2, o);
        d3 += __shfl_down_sync(0xffffffffu, d3, o);
    }
    __shared__ float sh[8][4];
    const int warp = threadIdx.x >> 5;
    const int tid  = threadIdx.x;
    if ((tid & 31) == 0) {
        sh[warp][0] = d0; sh[warp][1] = d1; sh[warp][2] = d2; sh[warp][3] = d3;
    }
    __syncthreads();

    __shared__ bool isLast;
    if (tid == 0) {
        float s0 = 0.f, s1 = 0.f, s2 = 0.f, s3 = 0.f;
#pragma unroll
        for (int w = 0; w < 8; w++) {
            s0 += sh[w][0]; s1 += sh[w][1]; s2 += sh[w][2]; s3 += sh[w][3];
        }
        g_part[blockIdx.x] = make_float4(s0, s1, s2, s3);
        __threadfence();
        unsigned old = atomicAdd(&g_count, 1u);
        isLast = (old == NBLK - 1);
    }
    __syncthreads();

    // ---- last block finalizes the scalar loss ----
    if (isLast) {
        double a0 = 0.0, a1 = 0.0, a2 = 0.0, a3 = 0.0;
#pragma unroll
        for (int i = tid; i < NBLK; i += 256) {
            const float4 p = g_part[i];
            a0 += (double)p.x; a1 += (double)p.y; a2 += (double)p.z; a3 += (double)p.w;
        }
#pragma unroll
        for (int o = 16; o > 0; o >>= 1) {
            a0 += __shfl_down_sync(0xffffffffu, a0, o);
            a1 += __shfl_down_sync(0xffffffffu, a1, o);
            a2 += __shfl_down_sync(0xffffffffu, a2, o);
            a3 += __shfl_down_sync(0xffffffffu, a3, o);
        }
        __shared__ double shd[8][4];
        if ((tid & 31) == 0) {
            shd[warp][0] = a0; shd[warp][1] = a1; shd[warp][2] = a2; shd[warp][3] = a3;
        }
        __syncthreads();
        if (tid == 0) {
            double s0 = 0.0, s1 = 0.0, s2 = 0.0, s3 = 0.0;
#pragma unroll
            for (int w = 0; w < 8; w++) {
                s0 += shd[w][0]; s1 += shd[w][1]; s2 += shd[w][2]; s3 += shd[w][3];
            }
            const double N = (double)HWTOT;
            const float mean = (float)(s3 / N);
            const float C3   = sqrtf(mean / WC0V_F);
            const double c3d = (double)C3;
            const double loss = (s0 + s1 * c3d + s2 * c3d * c3d) / N;
            out[0] = (float)loss;
            g_count = 0;            // reset for next graph replay
        }
    }
}

extern "C" void kernel_launch(void* const* d_in, const int* in_sizes, int n_in,
                              void* d_out, int out_size) {
    const int*   layout   = (const int*)d_in[0];
    const float* heat_ini = (const float*)d_in[1];
    const float* wc       = (const float*)d_in[2];
    const float* heat     = (const float*)d_in[3];
    const float* flow     = (const float*)d_in[4];
    float* out = (float*)d_out;

    energy_evp_main<<<NBLK, 256>>>(layout, heat_ini, wc, heat, flow, out);
}

// round 4
// speedup vs baseline: 1.1463x; 1.1463x over previous
#include <cuda_runtime.h>

#define HH 1024
#define WW 2048
#define HWTOT (HH * WW)
#define NBLK 2048

#define FLUXC    0.87890625f              // 300*H_STEP
#define F_COEF   0.002574920654296875f    // FLUX*H_STEP
#define WC0V_F ((float)(651.83 * 202.412 * 0.001 / 2.0))

// Cubic Taylor of K(tc) = FLUX0/(cp_a+cp_v*x_a)*(x_v-x_a)*C1*C2*C4*CT  about tc=0 (t=273.15K)
#define K_C0 (-5.517e-4f)
#define K_C1 ( 4.242e-5f)
#define K_C2 ( 1.399e-6f)
#define K_C3 ( 2.569e-8f)

// direction masks: extras per eq-code
#define CXP_MASK ((1u<<4)|(1u<<9)|(1u<<10))
#define CXN_MASK ((1u<<6)|(1u<<8)|(1u<<11))
#define CYP_MASK ((1u<<7)|(1u<<8)|(1u<<9))
#define CYN_MASK ((1u<<5)|(1u<<10)|(1u<<11))

__device__ float        g_sums[4] = {0.f, 0.f, 0.f, 0.f};  // S0, S1, S2, Swc
__device__ unsigned int g_count   = 0;

__device__ __forceinline__ int b_val(int raw, int r, int c) {
    if (r == 0 || r == HH - 1) return 3;
    if (c == WW - 1) return 3;
    if (c == 1) return 0;
    if ((r == 1 || r == HH - 2) && c >= 2) return 0;
    return raw;
}

__global__ __launch_bounds__(256, 6) void energy_evp_main(
    const int*   __restrict__ layout,
    const float* __restrict__ heat_ini,
    const float* __restrict__ wc,
    const float* __restrict__ heat,
    const float* __restrict__ flow,
    float*       __restrict__ out)
{
    const int g = blockIdx.x * blockDim.x + threadIdx.x;
    const int base = g * 4;
    const int r  = base >> 11;          // / WW
    const int c0 = base & (WW - 1);
    const int lane = threadIdx.x & 31;

    const int* __restrict__ braw = layout + HWTOT;

    const int4   b4  = *(const int4*)(braw + base);
    const int4   g4  = *(const int4*)(layout + base);
    const float4 h4  = *(const float4*)(heat + base);
    const float4 hi4 = *(const float4*)(heat_ini + base);
    const float4 w4  = *(const float4*)(wc + base);
    const float4 u4  = *(const float4*)(flow + base);
    const float4 v4  = *(const float4*)(flow + HWTOT + base);

    const int   brs[4] = {b4.x, b4.y, b4.z, b4.w};
    const int   ggs[4] = {g4.x, g4.y, g4.z, g4.w};
    const float hs[4]  = {h4.x, h4.y, h4.z, h4.w};
    const float his[4] = {hi4.x, hi4.y, hi4.z, hi4.w};
    const float ws[4]  = {w4.x, w4.y, w4.z, w4.w};
    const float us[4]  = {u4.x, u4.y, u4.z, u4.w};
    const float vs[4]  = {v4.x, v4.y, v4.z, v4.w};

    int   bs[4];
    float hb[4];
#pragma unroll
    for (int j = 0; j < 4; j++) {
        bs[j] = b_val(brs[j], r, c0 + j);
        hb[j] = (bs[j] == 1) ? 0.f : hs[j];
    }

    // horizontal neighbors via warp shuffle (warps are row-aligned: 128 cols)
    float leftN  = __shfl_up_sync(0xffffffffu, hb[3], 1);
    float rightN = __shfl_down_sync(0xffffffffu, hb[0], 1);
    if (lane == 0) {
        if (c0 > 0) {
            int bl = b_val(braw[base - 1], r, c0 - 1);
            leftN = (bl == 1) ? 0.f : heat[base - 1];
        } else leftN = 0.f;
    }
    if (lane == 31) {
        if (c0 + 4 < WW) {
            int brr = b_val(braw[base + 4], r, c0 + 4);
            rightN = (brr == 1) ? 0.f : heat[base + 4];
        } else rightN = 0.f;
    }

    float hbx[6];
    hbx[0] = leftN;
#pragma unroll
    for (int j = 0; j < 4; j++) hbx[j + 1] = hb[j];
    hbx[5] = rightN;

    // vertical neighbors (dy = 0 on first/last row via reflect pad)
    const bool has_y = (r > 0) && (r < HH - 1);
    float hbu[4] = {0.f, 0.f, 0.f, 0.f};
    float hbd[4] = {0.f, 0.f, 0.f, 0.f};
    if (has_y) {
        const int4   bu4 = *(const int4*)(braw + base - WW);
        const int4   bd4 = *(const int4*)(braw + base + WW);
        const float4 hu4 = *(const float4*)(heat + base - WW);
        const float4 hd4 = *(const float4*)(heat + base + WW);
        const int bus[4] = {bu4.x, bu4.y, bu4.z, bu4.w};
        const int bds[4] = {bd4.x, bd4.y, bd4.z, bd4.w};
        const float hus[4] = {hu4.x, hu4.y, hu4.z, hu4.w};
        const float hds[4] = {hd4.x, hd4.y, hd4.z, hd4.w};
#pragma unroll
        for (int j = 0; j < 4; j++) {
            hbu[j] = (b_val(bus[j], r - 1, c0 + j) == 1) ? 0.f : hus[j];
            hbd[j] = (b_val(bds[j], r + 1, c0 + j) == 1) ? 0.f : hds[j];
        }
    }

    float d0 = 0.f, d1 = 0.f, d2 = 0.f, d3 = 0.f;
    const bool edge_row = (r == 0) || (r == HH - 1);

#pragma unroll
    for (int j = 0; j < 4; j++) {
        const int c = c0 + j;
        const int b = bs[j];

        const float dx = (c == 0 || c == WW - 1) ? 0.f : 0.5f * (hbx[j + 2] - hbx[j]);
        const float dy = has_y ? 0.5f * (hbd[j] - hbu[j]) : 0.f;

        const float geom = edge_row ? 1.f : (float)ggs[j];
        const float f    = fabsf(geom - 1.f) * F_COEF;

        const float ad = his[j] - 0.001f * (us[j] * dx + vs[j] * dy);

        const float wcm  = (b > 3) ? 1.f : 0.f;
        const float wcbc = ws[j] * wcm;
        d3 += wcbc;

        // K(tc): cubic Taylor, tc = heat_bc (Celsius). m_dot = C3 * K.
        const float tc = hb[j];
        const float K  = fmaf(fmaf(fmaf(K_C3, tc, K_C2), tc, K_C1), tc, K_C0);

        // direction coefficients via bitmasks (no local-memory tables)
        const float cx = (float)(int)((CXP_MASK >> b) & 1u) - (float)(int)((CXN_MASK >> b) & 1u);
        const float cy = (float)(int)((CYP_MASK >> b) & 1u) - (float)(int)((CYN_MASK >> b) & 1u);
        const float al = (b >= 4) ? 1.f : 0.f;

        float A, Bc;
        if (b == 1) {
            A = -f; Bc = 0.f;
        } else {
            A  = ad + FLUXC * (cx * dx + cy * dy) + al * WC0V_F - f;
            Bc = -0.001f * al * K;
        }
        const float Aw = WC0V_F * wcm - wcbc;
        const float Bw = -K;

        d0 += A * A + Aw * Aw;
        d1 += 2.f * (A * Bc + Aw * Bw);
        d2 += Bc * Bc + Bw * Bw;

        out[1 + base + j]         = hb[j];
        out[1 + HWTOT + base + j] = (float)((b == 1) ? 0 : b);
    }

    // warp tree reduce (float)
#pragma unroll
    for (int o = 16; o > 0; o >>= 1) {
        d0 += __shfl_down_sync(0xffffffffu, d0, o);
        d1 += __shfl_down_sync(0xffffffffu, d1, o);
        d2 += __shfl_down_sync(0xffffffffu, d2, o);
        d3 += __shfl_down_sync(0xffffffffu, d3, o);
    }
    __shared__ float sh[8][4];
    const int warp = threadIdx.x >> 5;
    const int tid  = threadIdx.x;
    if (lane == 0) {
        sh[warp][0] = d0; sh[warp][1] = d1; sh[warp][2] = d2; sh[warp][3] = d3;
    }
    __syncthreads();

    if (tid == 0) {
        float s0 = 0.f, s1 = 0.f, s2 = 0.f, s3 = 0.f;
#pragma unroll
        for (int w = 0; w < 8; w++) {
            s0 += sh[w][0]; s1 += sh[w][1]; s2 += sh[w][2]; s3 += sh[w][3];
        }
        atomicAdd(&g_sums[0], s0);
        atomicAdd(&g_sums[1], s1);
        atomicAdd(&g_sums[2], s2);
        atomicAdd(&g_sums[3], s3);
        __threadfence();
        unsigned old = atomicAdd(&g_count, 1u);
        if (old == NBLK - 1) {
            const float S0 = __ldcg(&g_sums[0]);
            const float S1 = __ldcg(&g_sums[1]);
            const float S2 = __ldcg(&g_sums[2]);
            const float S3 = __ldcg(&g_sums[3]);
            const float invN = 1.f / (float)HWTOT;
            const float mean = S3 * invN;
            const float C3   = sqrtf(mean / WC0V_F);
            const float loss = (S0 + S1 * C3 + S2 * C3 * C3) * invN;
            out[0] = loss;
            // reset for next graph replay
            g_sums[0] = 0.f; g_sums[1] = 0.f; g_sums[2] = 0.f; g_sums[3] = 0.f;
            __threadfence();
            g_count = 0;
        }
    }
}

extern "C" void kernel_launch(void* const* d_in, const int* in_sizes, int n_in,
                              void* d_out, int out_size) {
    const int*   layout   = (const int*)d_in[0];
    const float* heat_ini = (const float*)d_in[1];
    const float* wc       = (const float*)d_in[2];
    const float* heat     = (const float*)d_in[3];
    const float* flow     = (const float*)d_in[4];
    float* out = (float*)d_out;

    energy_evp_main<<<NBLK, 256>>>(layout, heat_ini, wc, heat, flow, out);
}

// round 5
// speedup vs baseline: 1.2448x; 1.0859x over previous
#include <cuda_runtime.h>

#define HH 1024
#define WW 2048
#define HWTOT (HH * WW)
#define NBLK 2048

#define FLUXC    0.87890625f              // 300*H_STEP
#define F_COEF   0.002574920654296875f    // FLUX*H_STEP
#define WC0V_F ((float)(651.83 * 202.412 * 0.001 / 2.0))

// Cubic Taylor of K(tc) about tc=0 (t=273.15K)
#define K_C0 (-5.517e-4f)
#define K_C1 ( 4.242e-5f)
#define K_C2 ( 1.399e-6f)
#define K_C3 ( 2.569e-8f)

#define CXP_MASK ((1u<<4)|(1u<<9)|(1u<<10))
#define CXN_MASK ((1u<<6)|(1u<<8)|(1u<<11))
#define CYP_MASK ((1u<<7)|(1u<<8)|(1u<<9))
#define CYN_MASK ((1u<<5)|(1u<<10)|(1u<<11))

__device__ float        g_sums[4] = {0.f, 0.f, 0.f, 0.f};
__device__ unsigned int g_count   = 0;

__device__ __forceinline__ int b_val(int raw, int r, int c) {
    if (r == 0 || r == HH - 1) return 3;
    if (c == WW - 1) return 3;
    if (c == 1) return 0;
    if ((r == 1 || r == HH - 2) && c >= 2) return 0;
    return raw;
}

// store 4 values per thread into p[base..base+3] where p is 4B-aligned but
// (p+base) is 4 mod 16; shift window by 3 so lanes 0..30 do aligned STG.128
__device__ __forceinline__ void store_shifted(float* __restrict__ p, int base, int lane,
                                              float v0, float v1, float v2, float v3) {
    const float s1 = __shfl_down_sync(0xffffffffu, v0, 1);
    const float s2 = __shfl_down_sync(0xffffffffu, v1, 1);
    const float s3 = __shfl_down_sync(0xffffffffu, v2, 1);
    if (lane == 31) {
        p[base + 3] = v3;
    } else {
        *(float4*)(p + base + 3) = make_float4(v3, s1, s2, s3);
    }
    if (lane == 0) { p[base] = v0; p[base + 1] = v1; p[base + 2] = v2; }
}

template<bool FAST>
__device__ __forceinline__ void body(
    const int* __restrict__ layout, const float* __restrict__ heat_ini,
    const float* __restrict__ wc,   const float* __restrict__ heat,
    const float* __restrict__ flow, float* __restrict__ out,
    int base, int r, int c0, int lane,
    float& d0, float& d1, float& d2, float& d3)
{
    const int* __restrict__ braw = layout + HWTOT;

    const int4   b4  = *(const int4*)(braw + base);
    const int4   g4  = *(const int4*)(layout + base);
    const float4 h4  = *(const float4*)(heat + base);
    const float4 hi4 = *(const float4*)(heat_ini + base);
    const float4 w4  = *(const float4*)(wc + base);
    const float4 u4  = *(const float4*)(flow + base);
    const float4 v4  = *(const float4*)(flow + HWTOT + base);

    const int   brs[4] = {b4.x, b4.y, b4.z, b4.w};
    const int   ggs[4] = {g4.x, g4.y, g4.z, g4.w};
    const float hs[4]  = {h4.x, h4.y, h4.z, h4.w};
    const float his[4] = {hi4.x, hi4.y, hi4.z, hi4.w};
    const float ws[4]  = {w4.x, w4.y, w4.z, w4.w};
    const float us[4]  = {u4.x, u4.y, u4.z, u4.w};
    const float vs[4]  = {v4.x, v4.y, v4.z, v4.w};

    int   bs[4];
    float hb[4];
#pragma unroll
    for (int j = 0; j < 4; j++) {
        bs[j] = FAST ? brs[j] : b_val(brs[j], r, c0 + j);
        hb[j] = (bs[j] == 1) ? 0.f : hs[j];
    }

    // horizontal neighbors via warp shuffle (warps are row-aligned: 128 cols)
    float leftN  = __shfl_up_sync(0xffffffffu, hb[3], 1);
    float rightN = __shfl_down_sync(0xffffffffu, hb[0], 1);
    if (lane == 0) {
        if (FAST) {
            leftN = (braw[base - 1] == 1) ? 0.f : heat[base - 1];
        } else if (c0 > 0) {
            leftN = (b_val(braw[base - 1], r, c0 - 1) == 1) ? 0.f : heat[base - 1];
        } else leftN = 0.f;
    }
    if (lane == 31) {
        if (FAST) {
            rightN = (braw[base + 4] == 1) ? 0.f : heat[base + 4];
        } else if (c0 + 4 < WW) {
            rightN = (b_val(braw[base + 4], r, c0 + 4) == 1) ? 0.f : heat[base + 4];
        } else rightN = 0.f;
    }

    float hbx[6];
    hbx[0] = leftN;
#pragma unroll
    for (int j = 0; j < 4; j++) hbx[j + 1] = hb[j];
    hbx[5] = rightN;

    const bool has_y = FAST || ((r > 0) && (r < HH - 1));
    float hbu[4] = {0.f, 0.f, 0.f, 0.f};
    float hbd[4] = {0.f, 0.f, 0.f, 0.f};
    if (has_y) {
        const int4   bu4 = *(const int4*)(braw + base - WW);
        const int4   bd4 = *(const int4*)(braw + base + WW);
        const float4 hu4 = *(const float4*)(heat + base - WW);
        const float4 hd4 = *(const float4*)(heat + base + WW);
        const int bus[4] = {bu4.x, bu4.y, bu4.z, bu4.w};
        const int bds[4] = {bd4.x, bd4.y, bd4.z, bd4.w};
        const float hus[4] = {hu4.x, hu4.y, hu4.z, hu4.w};
        const float hds[4] = {hd4.x, hd4.y, hd4.z, hd4.w};
#pragma unroll
        for (int j = 0; j < 4; j++) {
            const int bu = FAST ? bus[j] : b_val(bus[j], r - 1, c0 + j);
            const int bd = FAST ? bds[j] : b_val(bds[j], r + 1, c0 + j);
            hbu[j] = (bu == 1) ? 0.f : hus[j];
            hbd[j] = (bd == 1) ? 0.f : hds[j];
        }
    }

    const bool edge_row = FAST ? false : ((r == 0) || (r == HH - 1));
    float eqv[4];

#pragma unroll
    for (int j = 0; j < 4; j++) {
        const int c = c0 + j;
        const int b = bs[j];

        float dx = 0.5f * (hbx[j + 2] - hbx[j]);
        if (!FAST && (c == 0 || c == WW - 1)) dx = 0.f;
        const float dy = has_y ? 0.5f * (hbd[j] - hbu[j]) : 0.f;

        const float geom = edge_row ? 1.f : (float)ggs[j];
        const float f    = fabsf(geom - 1.f) * F_COEF;

        const float ad = fmaf(-0.001f, fmaf(us[j], dx, vs[j] * dy), his[j]);

        const float wcm  = (b > 3) ? 1.f : 0.f;
        const float wcbc = ws[j] * wcm;
        d3 += wcbc;

        const float tc = hb[j];
        const float K  = fmaf(fmaf(fmaf(K_C3, tc, K_C2), tc, K_C1), tc, K_C0);

        const unsigned bb = 1u << b;
        const float cxdx = ((bb & CXP_MASK) ? dx : 0.f) - ((bb & CXN_MASK) ? dx : 0.f);
        const float cydy = ((bb & CYP_MASK) ? dy : 0.f) - ((bb & CYN_MASK) ? dy : 0.f);
        const float e    = (b >= 4) ? 1.f : 0.f;

        float A;
        if (b == 1) A = -f;
        else        A = fmaf(FLUXC, cxdx + cydy, ad) + fmaf(e, WC0V_F, -f);

        const float Aw = wcm * (WC0V_F - ws[j]);

        d0 += fmaf(A, A, Aw * Aw);
        const float tmp = fmaf(0.001f * e, A, Aw);
        d1 = fmaf(-2.f * K, tmp, d1);
        const float K2 = K * K;
        d2 += fmaf(1e-6f * e, K2, K2);

        eqv[j] = (float)((b == 1) ? 0 : b);
    }

    store_shifted(out + 1,         base, lane, hb[0], hb[1], hb[2], hb[3]);
    store_shifted(out + 1 + HWTOT, base, lane, eqv[0], eqv[1], eqv[2], eqv[3]);
}

__global__ __launch_bounds__(256, 6) void energy_evp_main(
    const int*   __restrict__ layout,
    const float* __restrict__ heat_ini,
    const float* __restrict__ wc,
    const float* __restrict__ heat,
    const float* __restrict__ flow,
    float*       __restrict__ out)
{
    const int g    = blockIdx.x * blockDim.x + threadIdx.x;
    const int base = g * 4;
    const int r    = base >> 11;
    const int c0   = base & (WW - 1);
    const int lane = threadIdx.x & 31;
    const int c0w  = c0 & ~127;

    float d0 = 0.f, d1 = 0.f, d2 = 0.f, d3 = 0.f;

    const bool fast = (r >= 3) && (r <= HH - 4) && (c0w >= 128) && (c0w <= WW - 256);
    if (fast) body<true >(layout, heat_ini, wc, heat, flow, out, base, r, c0, lane, d0, d1, d2, d3);
    else      body<false>(layout, heat_ini, wc, heat, flow, out, base, r, c0, lane, d0, d1, d2, d3);

    // warp tree reduce (float)
#pragma unroll
    for (int o = 16; o > 0; o >>= 1) {
        d0 += __shfl_down_sync(0xffffffffu, d0, o);
        d1 += __shfl_down_sync(0xffffffffu, d1, o);
        d2 += __shfl_down_sync(0xffffffffu, d2, o);
        d3 += __shfl_down_sync(0xffffffffu, d3, o);
    }
    __shared__ float sh[8][4];
    const int warp = threadIdx.x >> 5;
    const int tid  = threadIdx.x;
    if (lane == 0) {
        sh[warp][0] = d0; sh[warp][1] = d1; sh[warp][2] = d2; sh[warp][3] = d3;
    }
    __syncthreads();

    if (tid == 0) {
        float s0 = 0.f, s1 = 0.f, s2 = 0.f, s3 = 0.f;
#pragma unroll
        for (int w = 0; w < 8; w++) {
            s0 += sh[w][0]; s1 += sh[w][1]; s2 += sh[w][2]; s3 += sh[w][3];
        }
        atomicAdd(&g_sums[0], s0);
        atomicAdd(&g_sums[1], s1);
        atomicAdd(&g_sums[2], s2);
        atomicAdd(&g_sums[3], s3);
        __threadfence();
        unsigned old = atomicAdd(&g_count, 1u);
        if (old == NBLK - 1) {
            const float S0 = __ldcg(&g_sums[0]);
            const float S1 = __ldcg(&g_sums[1]);
            const float S2 = __ldcg(&g_sums[2]);
            const float S3 = __ldcg(&g_sums[3]);
            const float invN = 1.f / (float)HWTOT;
            const float mean = S3 * invN;
            const float C3   = sqrtf(mean / WC0V_F);
            const float loss = (S0 + S1 * C3 + S2 * C3 * C3) * invN;
            out[0] = loss;
            g_sums[0] = 0.f; g_sums[1] = 0.f; g_sums[2] = 0.f; g_sums[3] = 0.f;
            __threadfence();
            g_count = 0;
        }
    }
}

extern "C" void kernel_launch(void* const* d_in, const int* in_sizes, int n_in,
                              void* d_out, int out_size) {
    const int*   layout   = (const int*)d_in[0];
    const float* heat_ini = (const float*)d_in[1];
    const float* wc       = (const float*)d_in[2];
    const float* heat     = (const float*)d_in[3];
    const float* flow     = (const float*)d_in[4];
    float* out = (float*)d_out;

    energy_evp_main<<<NBLK, 256>>>(layout, heat_ini, wc, heat, flow, out);
}